// round 13
// baseline (speedup 1.0000x reference)
#include <cuda_runtime.h>
#include <cuda_fp16.h>

#define N_NODES_MAX 50000
#define IN_C  128
#define HID_C 64
#define OUT_C 32

// ---------------- scratch (no allocations allowed) ----------------
// g_deg counts IN-EDGES only (self loop handled as +1 at use sites).
// Zero-initialized at module load; re-zeroed by k_decode at the end of every
// launch, so every execution starts from deg==0.
__device__ int   g_deg [N_NODES_MAX];
__device__ int   g_rowstart[N_NODES_MAX];
__device__ int   g_cur [N_NODES_MAX];
__device__ float g_dinv[N_NODES_MAX];
__device__ int   g_esrc[1600000];                              // CSR src lists (cap 2x E)
__device__ __align__(16) __half g_xw1h[N_NODES_MAX * HID_C];   // x @ W1 (fp16 storage)
__device__ __align__(16) float  g_hw2 [N_NODES_MAX * OUT_C];   // relu(h) @ W2
__device__ __align__(16) __half g_z16 [N_NODES_MAX * OUT_C];   // z (fp16, decode only)

// ---------------- degree histogram (in-edges) ----------------
__global__ void k_deg(const int* __restrict__ dst, int E) {
    int e = blockIdx.x * blockDim.x + threadIdx.x;
    if (e < E) atomicAdd(&g_deg[dst[e]], 1);
}

// ---------------- single-kernel scan: rowstart = exclusive-prefix(deg) ----------------
__global__ __launch_bounds__(256) void k_scan(int n) {
    __shared__ int swarp[8];
    __shared__ int soff[8];
    int bid = blockIdx.x;
    int tid = threadIdx.x;
    int lane = tid & 31, warp = tid >> 5;

    // block offset = sum deg[0 .. bid*256)
    int limit = bid * 256;
    int s = 0;
    for (int j = tid; j < limit; j += 256) s += g_deg[j];
#pragma unroll
    for (int o = 16; o > 0; o >>= 1) s += __shfl_down_sync(0xffffffffu, s, o);
    if (lane == 0) soff[warp] = s;
    __syncthreads();
    if (tid < 8) {
        int t = soff[tid];
#pragma unroll
        for (int o = 4; o > 0; o >>= 1) t += __shfl_down_sync(0xffu, t, o);
        if (tid == 0) soff[0] = t;
    }
    __syncthreads();
    int off = soff[0];

    int i = bid * 256 + tid;
    int deg = (i < n) ? g_deg[i] : 0;
    int incl = deg;
#pragma unroll
    for (int o = 1; o < 32; o <<= 1) {
        int t = __shfl_up_sync(0xffffffffu, incl, o);
        if (lane >= o) incl += t;
    }
    if (lane == 31) swarp[warp] = incl;
    __syncthreads();
    if (tid < 8) {
        int t = swarp[tid];
        int si = t;
#pragma unroll
        for (int o = 1; o < 8; o <<= 1) {
            int u = __shfl_up_sync(0xffu, si, o);
            if (tid >= o) si += u;
        }
        swarp[tid] = si - t;   // exclusive warp offsets
    }
    __syncthreads();
    if (i < n) {
        int rs = off + swarp[warp] + (incl - deg);
        g_rowstart[i] = rs;
        g_cur[i] = rs;
        g_dinv[i] = rsqrtf((float)(deg + 1));
    }
}
__global__ void k_fill(const int* __restrict__ src, const int* __restrict__ dst, int E) {
    int e = blockIdx.x * blockDim.x + threadIdx.x;
    if (e < E) {
        int pos = atomicAdd(&g_cur[dst[e]], 1);
        g_esrc[pos] = src[e];
    }
}

// ---------------- helpers for tf32 mma ----------------
__device__ __forceinline__ unsigned int f32_to_tf32(float f) {
    unsigned int r;
    asm("cvt.rna.tf32.f32 %0, %1;" : "=r"(r) : "f"(f));
    return r;
}

// ---------------- GEMM1 (tensor core, tf32): xw1 = x@W1, fp16 store ----------------
__global__ __launch_bounds__(256) void k_gemm1(const float* __restrict__ x,
                                               const float* __restrict__ W1, int n) {
    __shared__ __align__(16) unsigned int sA[128 * 36];  // [row][k]
    __shared__ __align__(16) unsigned int sB[64 * 36];   // [col][k] (W1 transposed)

    const int tid = threadIdx.x;
    const int warp = tid >> 5, lane = tid & 31;
    const int g = lane >> 2, t = lane & 3;
    const int row0 = blockIdx.x * 128;
    const int wrow = warp * 16;

    float c[8][4];
#pragma unroll
    for (int i = 0; i < 8; i++)
#pragma unroll
        for (int j = 0; j < 4; j++) c[i][j] = 0.f;

#pragma unroll
    for (int kt = 0; kt < 4; kt++) {
        {
            int r = tid >> 3, f4 = tid & 7;
#pragma unroll
            for (int p = 0; p < 4; p++, r += 32) {
                int gr = row0 + r;
                float4 v = make_float4(0.f, 0.f, 0.f, 0.f);
                if (gr < n) v = *(const float4*)(x + (size_t)gr * IN_C + kt * 32 + f4 * 4);
                unsigned int* d = sA + r * 36 + f4 * 4;
                d[0] = f32_to_tf32(v.x);
                d[1] = f32_to_tf32(v.y);
                d[2] = f32_to_tf32(v.z);
                d[3] = f32_to_tf32(v.w);
            }
        }
        for (int i = tid; i < 32 * 64; i += 256) {
            int k = i >> 6, cc = i & 63;
            sB[cc * 36 + k] = f32_to_tf32(W1[(size_t)(kt * 32 + k) * HID_C + cc]);
        }
        __syncthreads();

#pragma unroll
        for (int ks = 0; ks < 4; ks++) {
            int kk = ks * 8;
            unsigned int a0 = sA[(wrow + g) * 36 + kk + t];
            unsigned int a1 = sA[(wrow + g + 8) * 36 + kk + t];
            unsigned int a2 = sA[(wrow + g) * 36 + kk + t + 4];
            unsigned int a3 = sA[(wrow + g + 8) * 36 + kk + t + 4];
#pragma unroll
            for (int nt = 0; nt < 8; nt++) {
                unsigned int b0 = sB[(nt * 8 + g) * 36 + kk + t];
                unsigned int b1 = sB[(nt * 8 + g) * 36 + kk + t + 4];
                asm volatile(
                    "mma.sync.aligned.m16n8k8.row.col.f32.tf32.tf32.f32 "
                    "{%0,%1,%2,%3}, {%4,%5,%6,%7}, {%8,%9}, {%0,%1,%2,%3};"
                    : "+f"(c[nt][0]), "+f"(c[nt][1]), "+f"(c[nt][2]), "+f"(c[nt][3])
                    : "r"(a0), "r"(a1), "r"(a2), "r"(a3), "r"(b0), "r"(b1));
            }
        }
        __syncthreads();
    }

    int r0 = row0 + wrow + g;
    int r1 = r0 + 8;
#pragma unroll
    for (int nt = 0; nt < 8; nt++) {
        int col = nt * 8 + 2 * t;
        if (r0 < n) {
            __half2 p = __floats2half2_rn(c[nt][0], c[nt][1]);
            *(__half2*)(g_xw1h + (size_t)r0 * HID_C + col) = p;
        }
        if (r1 < n) {
            __half2 p = __floats2half2_rn(c[nt][2], c[nt][3]);
            *(__half2*)(g_xw1h + (size_t)r1 * HID_C + col) = p;
        }
    }
}

// ---------------- fused: gather layer1 (+b1, relu) then @W2 -> g_hw2 ----------------
// 16 nodes / 256-thread block; 16 lanes per node. Edge chunks of 16:
// coalesced cooperative load of esrc+dinv, then width-16 shfl broadcast.
__global__ __launch_bounds__(256) void k_gather1_layer2(const float* __restrict__ b1,
                                                        const float* __restrict__ W2, int n) {
    __shared__ __align__(16) float sh[16 * 68];   // relu(agg1) rows, padded
    __shared__ float sW2[HID_C * OUT_C];          // sW2[k*32 + c]
    int tid = threadIdx.x;
    for (int i = tid; i < HID_C * OUT_C; i += 256) sW2[i] = W2[i];

    int grp = tid >> 4, l = tid & 15;             // node group, lane (4 dims = 8B fp16)
    unsigned hmask = ((tid & 31) >= 16) ? 0xffff0000u : 0x0000ffffu;
    int node = blockIdx.x * 16 + grp;
    if (node < n) {
        float dn = g_dinv[node];
        int beg = g_rowstart[node];
        int end = beg + g_deg[node];

        uint2 us = *(const uint2*)(g_xw1h + (size_t)node * HID_C + l * 4);
        float2 s0 = __half22float2(*(const __half2*)&us.x);
        float2 s1 = __half22float2(*(const __half2*)&us.y);
        float s = dn * dn;
        float4 bb = *(const float4*)(b1 + l * 4);
        float4 acc;
        acc.x = fmaf(s0.x, s, bb.x); acc.y = fmaf(s0.y, s, bb.y);
        acc.z = fmaf(s1.x, s, bb.z); acc.w = fmaf(s1.y, s, bb.w);

        int j = beg;
        while (j < end) {
            int rem = end - j;
            int m = rem < 16 ? rem : 16;
            int idx = 0; float w = 0.f;
            if (l < m) {
                idx = g_esrc[j + l];            // coalesced
                w = g_dinv[idx] * dn;
            }
            for (int q = 0; q < m; q++) {
                int   n0 = __shfl_sync(hmask, idx, q, 16);
                float w0 = __shfl_sync(hmask, w,   q, 16);
                uint2 u0 = *(const uint2*)(g_xw1h + (size_t)n0 * HID_C + l * 4);
                float2 a0 = __half22float2(*(const __half2*)&u0.x);
                float2 a1 = __half22float2(*(const __half2*)&u0.y);
                acc.x = fmaf(a0.x, w0, acc.x); acc.y = fmaf(a0.y, w0, acc.y);
                acc.z = fmaf(a1.x, w0, acc.z); acc.w = fmaf(a1.y, w0, acc.w);
            }
            j += 16;
        }
        float* dsth = sh + grp * 68 + l * 4;
        dsth[0] = fmaxf(acc.x, 0.f);
        dsth[1] = fmaxf(acc.y, 0.f);
        dsth[2] = fmaxf(acc.z, 0.f);
        dsth[3] = fmaxf(acc.w, 0.f);
    }
    __syncthreads();

    int nd = tid >> 4, c = tid & 15;
    int gnode = blockIdx.x * 16 + nd;
    if (gnode >= n) return;
    const float* hrow = sh + nd * 68;
    float a0 = 0.f, a1 = 0.f;
#pragma unroll 8
    for (int k = 0; k < HID_C; k++) {
        float hk = hrow[k];
        a0 = fmaf(hk, sW2[k * OUT_C + c], a0);
        a1 = fmaf(hk, sW2[k * OUT_C + c + 16], a1);
    }
    g_hw2[(size_t)gnode * OUT_C + c]      = a0;
    g_hw2[(size_t)gnode * OUT_C + c + 16] = a1;
}

// ---------------- gather layer2 (+b2) -> z (fp16) ----------------
// 32 nodes / block; 8 lanes per node. Edge chunks of 8, width-8 shfl broadcast.
__global__ __launch_bounds__(256) void k_gather2(const float* __restrict__ b2, int n) {
    int tid = threadIdx.x;
    int grp = tid >> 3, l = tid & 7;
    unsigned qmask = 0xffu << (((tid & 31) >> 3) * 8);
    int node = blockIdx.x * 32 + grp;
    if (node >= n) return;

    float dn = g_dinv[node];
    int beg = g_rowstart[node];
    int end = beg + g_deg[node];

    float4 acc = *(const float4*)(g_hw2 + (size_t)node * OUT_C + l * 4);
    float s = dn * dn;
    float4 bb = *(const float4*)(b2 + l * 4);
    acc.x = fmaf(acc.x, s, bb.x); acc.y = fmaf(acc.y, s, bb.y);
    acc.z = fmaf(acc.z, s, bb.z); acc.w = fmaf(acc.w, s, bb.w);

    int j = beg;
    while (j < end) {
        int rem = end - j;
        int m = rem < 8 ? rem : 8;
        int idx = 0; float w = 0.f;
        if (l < m) {
            idx = g_esrc[j + l];               // coalesced
            w = g_dinv[idx] * dn;
        }
        for (int q = 0; q < m; q++) {
            int   n0 = __shfl_sync(qmask, idx, q, 8);
            float w0 = __shfl_sync(qmask, w,   q, 8);
            float4 v0 = *(const float4*)(g_hw2 + (size_t)n0 * OUT_C + l * 4);
            acc.x = fmaf(v0.x, w0, acc.x); acc.y = fmaf(v0.y, w0, acc.y);
            acc.z = fmaf(v0.z, w0, acc.z); acc.w = fmaf(v0.w, w0, acc.w);
        }
        j += 8;
    }
    __half2 p0 = __floats2half2_rn(acc.x, acc.y);
    __half2 p1 = __floats2half2_rn(acc.z, acc.w);
    uint2 u;
    u.x = *(const unsigned int*)&p0;
    u.y = *(const unsigned int*)&p1;
    *(uint2*)(g_z16 + (size_t)node * OUT_C + l * 4) = u;
}

// ---------------- decode: logits[e] = dot(z[a], z[b]) (fp16 z, fp32 math) ----------------
// Also resets g_deg to 0 for the next launch (keeps per-call state invariant).
__global__ __launch_bounds__(256) void k_decode(const int* __restrict__ de, int E,
                                                float* __restrict__ out, int n) {
    int g = blockIdx.x * blockDim.x + threadIdx.x;
    if (g < n) g_deg[g] = 0;   // restore deg==0 invariant for next call
    int e = g >> 2, t = g & 3;
    bool valid = (e < E);
    if (!valid) e = 0;
    int a = 0, b = 0;
    if (t == 0) { a = de[e]; b = de[E + e]; }
    a = __shfl_sync(0xffffffffu, a, 0, 4);
    b = __shfl_sync(0xffffffffu, b, 0, 4);
    uint4 ua = *(const uint4*)(g_z16 + (size_t)a * OUT_C + t * 8);
    uint4 ub = *(const uint4*)(g_z16 + (size_t)b * OUT_C + t * 8);
    float p = 0.f;
    const unsigned int* pa = &ua.x;
    const unsigned int* pb = &ub.x;
#pragma unroll
    for (int i = 0; i < 4; i++) {
        float2 fa = __half22float2(*(const __half2*)&pa[i]);
        float2 fb = __half22float2(*(const __half2*)&pb[i]);
        p = fmaf(fa.x, fb.x, p);
        p = fmaf(fa.y, fb.y, p);
    }
    p += __shfl_down_sync(0xffffffffu, p, 2, 4);
    p += __shfl_down_sync(0xffffffffu, p, 1, 4);
    if (valid && t == 0) out[e] = p;
}

// ---------------- launch ----------------
extern "C" void kernel_launch(void* const* d_in, const int* in_sizes, int n_in,
                              void* d_out, int out_size) {
    const float* x  = (const float*)d_in[0];
    const float* W1 = (const float*)d_in[1];
    const float* b1 = (const float*)d_in[2];
    const float* W2 = (const float*)d_in[3];
    const float* b2 = (const float*)d_in[4];
    const int*   ei = (const int*)d_in[5];
    const int*   de = (const int*)d_in[6];

    int N  = in_sizes[0] / IN_C;
    int E  = in_sizes[5] / 2;
    int Ed = in_sizes[6] / 2;
    const int* src = ei;
    const int* dst = ei + E;
    float* out = (float*)d_out;

    int nb = (N + 255) / 256;

    k_deg<<<(E + 255) / 256, 256>>>(dst, E);
    k_scan<<<nb, 256>>>(N);
    k_fill<<<(E + 255) / 256, 256>>>(src, dst, E);

    k_gemm1<<<(N + 127) / 128, 256>>>(x, W1, N);

    k_gather1_layer2<<<(N + 15) / 16, 256>>>(b1, W2, N);
    k_gather2<<<(N + 31) / 32, 256>>>(b2, N);

    long long thd = (long long)Ed * 4;
    k_decode<<<(unsigned)((thd + 255) / 256), 256>>>(de, Ed, out, N);
}

// round 14
// speedup vs baseline: 1.1281x; 1.1281x over previous
#include <cuda_runtime.h>
#include <cuda_fp16.h>

#define N_NODES_MAX 50000
#define IN_C  128
#define HID_C 64
#define OUT_C 32

// ---------------- scratch (no allocations allowed) ----------------
// g_deg counts IN-EDGES only (self loop handled as +1 at use sites).
// Zero-initialized at module load; re-zeroed by k_decode at the end of every
// launch, so every execution starts from deg==0.
__device__ int   g_deg [N_NODES_MAX];
__device__ int   g_rowstart[N_NODES_MAX];
__device__ int   g_cur [N_NODES_MAX];
__device__ float g_dinv[N_NODES_MAX];
__device__ __align__(16) int2  g_epair[1600000];               // CSR: (src, dinv[src] bits)
__device__ __align__(16) __half g_xw1h[N_NODES_MAX * HID_C];   // x @ W1 (fp16 storage)
__device__ __align__(16) float  g_hw2 [N_NODES_MAX * OUT_C];   // relu(h) @ W2
__device__ __align__(16) __half g_z16 [N_NODES_MAX * OUT_C];   // z (fp16, decode only)

// ---------------- degree histogram (in-edges) ----------------
__global__ void k_deg(const int* __restrict__ dst, int E) {
    int e = blockIdx.x * blockDim.x + threadIdx.x;
    if (e < E) atomicAdd(&g_deg[dst[e]], 1);
}

// ---------------- single-kernel scan: rowstart = exclusive-prefix(deg) ----------------
__global__ __launch_bounds__(256) void k_scan(int n) {
    __shared__ int swarp[8];
    __shared__ int soff[8];
    int bid = blockIdx.x;
    int tid = threadIdx.x;
    int lane = tid & 31, warp = tid >> 5;

    // block offset = sum deg[0 .. bid*256)
    int limit = bid * 256;
    int s = 0;
    for (int j = tid; j < limit; j += 256) s += g_deg[j];
#pragma unroll
    for (int o = 16; o > 0; o >>= 1) s += __shfl_down_sync(0xffffffffu, s, o);
    if (lane == 0) soff[warp] = s;
    __syncthreads();
    if (tid < 8) {
        int t = soff[tid];
#pragma unroll
        for (int o = 4; o > 0; o >>= 1) t += __shfl_down_sync(0xffu, t, o);
        if (tid == 0) soff[0] = t;
    }
    __syncthreads();
    int off = soff[0];

    int i = bid * 256 + tid;
    int deg = (i < n) ? g_deg[i] : 0;
    int incl = deg;
#pragma unroll
    for (int o = 1; o < 32; o <<= 1) {
        int t = __shfl_up_sync(0xffffffffu, incl, o);
        if (lane >= o) incl += t;
    }
    if (lane == 31) swarp[warp] = incl;
    __syncthreads();
    if (tid < 8) {
        int t = swarp[tid];
        int si = t;
#pragma unroll
        for (int o = 1; o < 8; o <<= 1) {
            int u = __shfl_up_sync(0xffu, si, o);
            if (tid >= o) si += u;
        }
        swarp[tid] = si - t;   // exclusive warp offsets
    }
    __syncthreads();
    if (i < n) {
        int rs = off + swarp[warp] + (incl - deg);
        g_rowstart[i] = rs;
        g_cur[i] = rs;
        g_dinv[i] = rsqrtf((float)(deg + 1));
    }
}

// ---------------- CSR fill: store (src, dinv[src]) pairs ----------------
__global__ void k_fill(const int* __restrict__ src, const int* __restrict__ dst, int E) {
    int e = blockIdx.x * blockDim.x + threadIdx.x;
    if (e < E) {
        int s = src[e];
        float ds = g_dinv[s];
        int pos = atomicAdd(&g_cur[dst[e]], 1);
        g_epair[pos] = make_int2(s, __float_as_int(ds));
    }
}

// ---------------- helpers for tf32 mma ----------------
__device__ __forceinline__ unsigned int f32_to_tf32(float f) {
    unsigned int r;
    asm("cvt.rna.tf32.f32 %0, %1;" : "=r"(r) : "f"(f));
    return r;
}

// ---------------- GEMM1 (tensor core, tf32): xw1 = x@W1, fp16 store ----------------
__global__ __launch_bounds__(256) void k_gemm1(const float* __restrict__ x,
                                               const float* __restrict__ W1, int n) {
    __shared__ __align__(16) unsigned int sA[128 * 36];  // [row][k]
    __shared__ __align__(16) unsigned int sB[64 * 36];   // [col][k] (W1 transposed)

    const int tid = threadIdx.x;
    const int warp = tid >> 5, lane = tid & 31;
    const int g = lane >> 2, t = lane & 3;
    const int row0 = blockIdx.x * 128;
    const int wrow = warp * 16;

    float c[8][4];
#pragma unroll
    for (int i = 0; i < 8; i++)
#pragma unroll
        for (int j = 0; j < 4; j++) c[i][j] = 0.f;

#pragma unroll
    for (int kt = 0; kt < 4; kt++) {
        {
            int r = tid >> 3, f4 = tid & 7;
#pragma unroll
            for (int p = 0; p < 4; p++, r += 32) {
                int gr = row0 + r;
                float4 v = make_float4(0.f, 0.f, 0.f, 0.f);
                if (gr < n) v = *(const float4*)(x + (size_t)gr * IN_C + kt * 32 + f4 * 4);
                unsigned int* d = sA + r * 36 + f4 * 4;
                d[0] = f32_to_tf32(v.x);
                d[1] = f32_to_tf32(v.y);
                d[2] = f32_to_tf32(v.z);
                d[3] = f32_to_tf32(v.w);
            }
        }
        for (int i = tid; i < 32 * 64; i += 256) {
            int k = i >> 6, cc = i & 63;
            sB[cc * 36 + k] = f32_to_tf32(W1[(size_t)(kt * 32 + k) * HID_C + cc]);
        }
        __syncthreads();

#pragma unroll
        for (int ks = 0; ks < 4; ks++) {
            int kk = ks * 8;
            unsigned int a0 = sA[(wrow + g) * 36 + kk + t];
            unsigned int a1 = sA[(wrow + g + 8) * 36 + kk + t];
            unsigned int a2 = sA[(wrow + g) * 36 + kk + t + 4];
            unsigned int a3 = sA[(wrow + g + 8) * 36 + kk + t + 4];
#pragma unroll
            for (int nt = 0; nt < 8; nt++) {
                unsigned int b0 = sB[(nt * 8 + g) * 36 + kk + t];
                unsigned int b1 = sB[(nt * 8 + g) * 36 + kk + t + 4];
                asm volatile(
                    "mma.sync.aligned.m16n8k8.row.col.f32.tf32.tf32.f32 "
                    "{%0,%1,%2,%3}, {%4,%5,%6,%7}, {%8,%9}, {%0,%1,%2,%3};"
                    : "+f"(c[nt][0]), "+f"(c[nt][1]), "+f"(c[nt][2]), "+f"(c[nt][3])
                    : "r"(a0), "r"(a1), "r"(a2), "r"(a3), "r"(b0), "r"(b1));
            }
        }
        __syncthreads();
    }

    int r0 = row0 + wrow + g;
    int r1 = r0 + 8;
#pragma unroll
    for (int nt = 0; nt < 8; nt++) {
        int col = nt * 8 + 2 * t;
        if (r0 < n) {
            __half2 p = __floats2half2_rn(c[nt][0], c[nt][1]);
            *(__half2*)(g_xw1h + (size_t)r0 * HID_C + col) = p;
        }
        if (r1 < n) {
            __half2 p = __floats2half2_rn(c[nt][2], c[nt][3]);
            *(__half2*)(g_xw1h + (size_t)r1 * HID_C + col) = p;
        }
    }
}

// accumulate one fp16 row segment (uint2 = 4 halves) scaled by w
__device__ __forceinline__ void acc_row16(float4& acc, uint2 u, float w) {
    float2 a0 = __half22float2(*(const __half2*)&u.x);
    float2 a1 = __half22float2(*(const __half2*)&u.y);
    acc.x = fmaf(a0.x, w, acc.x); acc.y = fmaf(a0.y, w, acc.y);
    acc.z = fmaf(a1.x, w, acc.z); acc.w = fmaf(a1.y, w, acc.w);
}

// ---------------- fused: gather layer1 (+b1, relu) then @W2 -> g_hw2 ----------------
// 16 nodes / 256-thread block; 16 lanes per node. Edge records are (src, dinv)
// pairs (8B broadcast load); 4-edge unroll for MLP=4 on the row gathers.
__global__ __launch_bounds__(256) void k_gather1_layer2(const float* __restrict__ b1,
                                                        const float* __restrict__ W2, int n) {
    __shared__ __align__(16) float sh[16 * 68];   // relu(agg1) rows, padded
    __shared__ float sW2[HID_C * OUT_C];          // sW2[k*32 + c]
    int tid = threadIdx.x;
    for (int i = tid; i < HID_C * OUT_C; i += 256) sW2[i] = W2[i];

    int grp = tid >> 4, l = tid & 15;             // node group, lane (4 dims = 8B fp16)
    int node = blockIdx.x * 16 + grp;
    if (node < n) {
        float dn = g_dinv[node];
        int beg = g_rowstart[node];
        int end = beg + g_deg[node];

        uint2 us = *(const uint2*)(g_xw1h + (size_t)node * HID_C + l * 4);
        float s = dn * dn;
        float4 bb = *(const float4*)(b1 + l * 4);
        float4 acc = make_float4(bb.x, bb.y, bb.z, bb.w);
        acc_row16(acc, us, s);

        int j = beg;
        for (; j + 3 < end; j += 4) {
            int2 p0 = g_epair[j];
            int2 p1 = g_epair[j + 1];
            int2 p2 = g_epair[j + 2];
            int2 p3 = g_epair[j + 3];
            uint2 u0 = *(const uint2*)(g_xw1h + (size_t)p0.x * HID_C + l * 4);
            uint2 u1 = *(const uint2*)(g_xw1h + (size_t)p1.x * HID_C + l * 4);
            uint2 u2 = *(const uint2*)(g_xw1h + (size_t)p2.x * HID_C + l * 4);
            uint2 u3 = *(const uint2*)(g_xw1h + (size_t)p3.x * HID_C + l * 4);
            acc_row16(acc, u0, __int_as_float(p0.y) * dn);
            acc_row16(acc, u1, __int_as_float(p1.y) * dn);
            acc_row16(acc, u2, __int_as_float(p2.y) * dn);
            acc_row16(acc, u3, __int_as_float(p3.y) * dn);
        }
        for (; j < end; j++) {
            int2 p0 = g_epair[j];
            uint2 u0 = *(const uint2*)(g_xw1h + (size_t)p0.x * HID_C + l * 4);
            acc_row16(acc, u0, __int_as_float(p0.y) * dn);
        }
        float* dsth = sh + grp * 68 + l * 4;
        dsth[0] = fmaxf(acc.x, 0.f);
        dsth[1] = fmaxf(acc.y, 0.f);
        dsth[2] = fmaxf(acc.z, 0.f);
        dsth[3] = fmaxf(acc.w, 0.f);
    }
    __syncthreads();

    int nd = tid >> 4, c = tid & 15;
    int gnode = blockIdx.x * 16 + nd;
    if (gnode >= n) return;
    const float* hrow = sh + nd * 68;
    float a0 = 0.f, a1 = 0.f;
#pragma unroll 8
    for (int k = 0; k < HID_C; k++) {
        float hk = hrow[k];
        a0 = fmaf(hk, sW2[k * OUT_C + c], a0);
        a1 = fmaf(hk, sW2[k * OUT_C + c + 16], a1);
    }
    g_hw2[(size_t)gnode * OUT_C + c]      = a0;
    g_hw2[(size_t)gnode * OUT_C + c + 16] = a1;
}

// ---------------- gather layer2 (+b2) -> z (fp16) ----------------
// 32 nodes / block; 8 lanes per node (float4). 4-edge unroll.
__global__ __launch_bounds__(256) void k_gather2(const float* __restrict__ b2, int n) {
    int tid = threadIdx.x;
    int grp = tid >> 3, l = tid & 7;
    int node = blockIdx.x * 32 + grp;
    if (node >= n) return;

    float dn = g_dinv[node];
    int beg = g_rowstart[node];
    int end = beg + g_deg[node];

    float4 acc = *(const float4*)(g_hw2 + (size_t)node * OUT_C + l * 4);
    float s = dn * dn;
    float4 bb = *(const float4*)(b2 + l * 4);
    acc.x = fmaf(acc.x, s, bb.x); acc.y = fmaf(acc.y, s, bb.y);
    acc.z = fmaf(acc.z, s, bb.z); acc.w = fmaf(acc.w, s, bb.w);

    int j = beg;
    for (; j + 3 < end; j += 4) {
        int2 p0 = g_epair[j];
        int2 p1 = g_epair[j + 1];
        int2 p2 = g_epair[j + 2];
        int2 p3 = g_epair[j + 3];
        float4 v0 = *(const float4*)(g_hw2 + (size_t)p0.x * OUT_C + l * 4);
        float4 v1 = *(const float4*)(g_hw2 + (size_t)p1.x * OUT_C + l * 4);
        float4 v2 = *(const float4*)(g_hw2 + (size_t)p2.x * OUT_C + l * 4);
        float4 v3 = *(const float4*)(g_hw2 + (size_t)p3.x * OUT_C + l * 4);
        float w0 = __int_as_float(p0.y) * dn;
        float w1 = __int_as_float(p1.y) * dn;
        float w2 = __int_as_float(p2.y) * dn;
        float w3 = __int_as_float(p3.y) * dn;
        acc.x = fmaf(v0.x, w0, acc.x); acc.y = fmaf(v0.y, w0, acc.y);
        acc.z = fmaf(v0.z, w0, acc.z); acc.w = fmaf(v0.w, w0, acc.w);
        acc.x = fmaf(v1.x, w1, acc.x); acc.y = fmaf(v1.y, w1, acc.y);
        acc.z = fmaf(v1.z, w1, acc.z); acc.w = fmaf(v1.w, w1, acc.w);
        acc.x = fmaf(v2.x, w2, acc.x); acc.y = fmaf(v2.y, w2, acc.y);
        acc.z = fmaf(v2.z, w2, acc.z); acc.w = fmaf(v2.w, w2, acc.w);
        acc.x = fmaf(v3.x, w3, acc.x); acc.y = fmaf(v3.y, w3, acc.y);
        acc.z = fmaf(v3.z, w3, acc.z); acc.w = fmaf(v3.w, w3, acc.w);
    }
    for (; j < end; j++) {
        int2 p0 = g_epair[j];
        float w0 = __int_as_float(p0.y) * dn;
        float4 v0 = *(const float4*)(g_hw2 + (size_t)p0.x * OUT_C + l * 4);
        acc.x = fmaf(v0.x, w0, acc.x); acc.y = fmaf(v0.y, w0, acc.y);
        acc.z = fmaf(v0.z, w0, acc.z); acc.w = fmaf(v0.w, w0, acc.w);
    }
    __half2 p0 = __floats2half2_rn(acc.x, acc.y);
    __half2 p1 = __floats2half2_rn(acc.z, acc.w);
    uint2 u;
    u.x = *(const unsigned int*)&p0;
    u.y = *(const unsigned int*)&p1;
    *(uint2*)(g_z16 + (size_t)node * OUT_C + l * 4) = u;
}

// ---------------- decode: logits[e] = dot(z[a], z[b]) (fp16 z, fp32 math) ----------------
// Also resets g_deg to 0 for the next launch (keeps per-call state invariant).
__global__ __launch_bounds__(256) void k_decode(const int* __restrict__ de, int E,
                                                float* __restrict__ out, int n) {
    int g = blockIdx.x * blockDim.x + threadIdx.x;
    if (g < n) g_deg[g] = 0;   // restore deg==0 invariant for next call
    int e = g >> 2, t = g & 3;
    bool valid = (e < E);
    if (!valid) e = 0;
    int a = 0, b = 0;
    if (t == 0) { a = de[e]; b = de[E + e]; }
    a = __shfl_sync(0xffffffffu, a, 0, 4);
    b = __shfl_sync(0xffffffffu, b, 0, 4);
    uint4 ua = *(const uint4*)(g_z16 + (size_t)a * OUT_C + t * 8);
    uint4 ub = *(const uint4*)(g_z16 + (size_t)b * OUT_C + t * 8);
    float p = 0.f;
    const unsigned int* pa = &ua.x;
    const unsigned int* pb = &ub.x;
#pragma unroll
    for (int i = 0; i < 4; i++) {
        float2 fa = __half22float2(*(const __half2*)&pa[i]);
        float2 fb = __half22float2(*(const __half2*)&pb[i]);
        p = fmaf(fa.x, fb.x, p);
        p = fmaf(fa.y, fb.y, p);
    }
    p += __shfl_down_sync(0xffffffffu, p, 2, 4);
    p += __shfl_down_sync(0xffffffffu, p, 1, 4);
    if (valid && t == 0) out[e] = p;
}

// ---------------- launch ----------------
extern "C" void kernel_launch(void* const* d_in, const int* in_sizes, int n_in,
                              void* d_out, int out_size) {
    const float* x  = (const float*)d_in[0];
    const float* W1 = (const float*)d_in[1];
    const float* b1 = (const float*)d_in[2];
    const float* W2 = (const float*)d_in[3];
    const float* b2 = (const float*)d_in[4];
    const int*   ei = (const int*)d_in[5];
    const int*   de = (const int*)d_in[6];

    int N  = in_sizes[0] / IN_C;
    int E  = in_sizes[5] / 2;
    int Ed = in_sizes[6] / 2;
    const int* src = ei;
    const int* dst = ei + E;
    float* out = (float*)d_out;

    int nb = (N + 255) / 256;

    k_deg<<<(E + 255) / 256, 256>>>(dst, E);
    k_scan<<<nb, 256>>>(N);
    k_fill<<<(E + 255) / 256, 256>>>(src, dst, E);

    k_gemm1<<<(N + 127) / 128, 256>>>(x, W1, N);

    k_gather1_layer2<<<(N + 15) / 16, 256>>>(b1, W2, N);
    k_gather2<<<(N + 31) / 32, 256>>>(b2, N);

    long long thd = (long long)Ed * 4;
    k_decode<<<(unsigned)((thd + 255) / 256), 256>>>(de, Ed, out, N);
}